// round 2
// baseline (speedup 1.0000x reference)
#include <cuda_runtime.h>
#include <math.h>

#define BATCH   4
#define SEQ     4096
#define EMB     1024
#define HEADS   16
#define HD      64
#define DFF     4096
#define WIN     128
#define NB      (SEQ / WIN)
#define M_TOK   (BATCH * SEQ)   /* 16384 rows of tokens */

/* ---------------- scratch (static device allocations) ---------------- */
__device__ float g_xnorm[(size_t)M_TOK * EMB];    /*  64 MB : LN1 out, later LN2 out */
__device__ float g_qkv[(size_t)M_TOK * 3 * EMB];  /* 192 MB : fused qkv activations  */
__device__ float g_attn[(size_t)M_TOK * EMB];     /*  64 MB : attention out (B,N,C)  */
__device__ float g_hbuf[(size_t)M_TOK * DFF];     /* 256 MB : gelu(fc1) activations  */

/* ---------------- block reduction helper ---------------- */
__device__ __forceinline__ float block_sum_1024(float v, float* sh)
{
    /* 256 threads = 8 warps */
    #pragma unroll
    for (int o = 16; o > 0; o >>= 1)
        v += __shfl_xor_sync(0xFFFFFFFFu, v, o);
    const int wid = threadIdx.x >> 5;
    const int lane = threadIdx.x & 31;
    if (lane == 0) sh[wid] = v;
    __syncthreads();
    if (wid == 0) {
        float t = (lane < 8) ? sh[lane] : 0.f;
        #pragma unroll
        for (int o = 4; o > 0; o >>= 1)
            t += __shfl_xor_sync(0xFFFFFFFFu, t, o);
        if (lane == 0) sh[8] = t;
    }
    __syncthreads();
    float r = sh[8];
    __syncthreads();   /* protect shared reuse by a second call */
    return r;
}

/* ---------------- LayerNorm: one block per row of 1024 ---------------- */
__global__ __launch_bounds__(256)
void ln_kernel(const float* __restrict__ x, const float* __restrict__ w,
               const float* __restrict__ b, float* __restrict__ out)
{
    __shared__ float sh[9];
    const int row = blockIdx.x;
    const int t = threadIdx.x;
    const float* xr = x + (size_t)row * EMB;

    float4 v = *(const float4*)(xr + t * 4);
    float mu = block_sum_1024(v.x + v.y + v.z + v.w, sh) * (1.f / EMB);

    float d0 = v.x - mu, d1 = v.y - mu, d2 = v.z - mu, d3 = v.w - mu;
    float var = block_sum_1024(d0 * d0 + d1 * d1 + d2 * d2 + d3 * d3, sh) * (1.f / EMB);
    float rs = rsqrtf(var + 1e-5f);

    float4 wv = *(const float4*)(w + t * 4);
    float4 bv = *(const float4*)(b + t * 4);
    float4 o;
    o.x = d0 * rs * wv.x + bv.x;
    o.y = d1 * rs * wv.y + bv.y;
    o.z = d2 * rs * wv.z + bv.z;
    o.w = d3 * rs * wv.w + bv.w;
    *(float4*)(out + (size_t)row * EMB + t * 4) = o;
}

/* ---------------- SGEMM: C[M,N] = A[M,K] @ B[N,K]^T + bias (+epilogue) --------- */
/* 128x128 tile, BK=8, 256 threads, 8x8 per thread */
#define EPI_NONE 0
#define EPI_ADD  1
#define EPI_GELU 2

template<int EPI>
__global__ __launch_bounds__(256, 2)
void sgemm_kernel(const float* __restrict__ A, const float* __restrict__ B,
                  const float* __restrict__ bias, const float* __restrict__ R,
                  float* __restrict__ C, int M, int N, int K)
{
    __shared__ float As[8][128];
    __shared__ float Bs[8][128];
    const int tid = threadIdx.x;
    const int bm = blockIdx.y * 128;
    const int bn = blockIdx.x * 128;

    const int lr = tid >> 1;            /* 0..127 tile row for loads */
    const int lc = (tid & 1) << 2;      /* 0 or 4 k-offset */
    const float* Ap = A + (size_t)(bm + lr) * K + lc;
    const float* Bp = B + (size_t)(bn + lr) * K + lc;

    const int rm = (tid >> 4) << 3;     /* 0..120 */
    const int rn = (tid & 15) << 3;     /* 0..120 */

    float acc[8][8];
    #pragma unroll
    for (int i = 0; i < 8; i++)
        #pragma unroll
        for (int j = 0; j < 8; j++) acc[i][j] = 0.f;

    for (int k0 = 0; k0 < K; k0 += 8) {
        float4 av = *(const float4*)(Ap + k0);
        float4 bv = *(const float4*)(Bp + k0);
        As[lc + 0][lr] = av.x; As[lc + 1][lr] = av.y;
        As[lc + 2][lr] = av.z; As[lc + 3][lr] = av.w;
        Bs[lc + 0][lr] = bv.x; Bs[lc + 1][lr] = bv.y;
        Bs[lc + 2][lr] = bv.z; Bs[lc + 3][lr] = bv.w;
        __syncthreads();

        #pragma unroll
        for (int kk = 0; kk < 8; kk++) {
            float a[8], bb[8];
            *(float4*)(a)      = *(const float4*)(&As[kk][rm]);
            *(float4*)(a + 4)  = *(const float4*)(&As[kk][rm + 4]);
            *(float4*)(bb)     = *(const float4*)(&Bs[kk][rn]);
            *(float4*)(bb + 4) = *(const float4*)(&Bs[kk][rn + 4]);
            #pragma unroll
            for (int i = 0; i < 8; i++)
                #pragma unroll
                for (int j = 0; j < 8; j++)
                    acc[i][j] += a[i] * bb[j];
        }
        __syncthreads();
    }

    #pragma unroll
    for (int i = 0; i < 8; i++) {
        const size_t rowoff = (size_t)(bm + rm + i) * N + bn + rn;
        #pragma unroll
        for (int j = 0; j < 8; j++) {
            float c = acc[i][j] + bias[bn + rn + j];
            if (EPI == EPI_ADD)  c += R[rowoff + j];
            if (EPI == EPI_GELU) c = 0.5f * c * (1.f + erff(c * 0.70710678118654752f));
            C[rowoff + j] = c;
        }
    }
}

/* ---------------- local windowed attention ----------------
 * grid: (NB, B*HEADS); 128 threads, one query row per thread.
 * Window = blocks [bi-1, bi, bi+1]; out-of-range blocks are skipped
 * (exactly equivalent to the -inf mask in the reference).
 * K/V streamed through smem in 64-row chunks; online softmax in regs. */
__global__ __launch_bounds__(128)
void lattn_kernel(const float* __restrict__ qkv, float* __restrict__ out)
{
    __shared__ float ks[64][64];
    __shared__ float vs[64][64];

    const int bi = blockIdx.x;           /* window block 0..31   */
    const int bh = blockIdx.y;           /* 0..63                */
    const int b = bh >> 4, h = bh & 15;
    const int tid = threadIdx.x;
    const int pos = bi * WIN + tid;

    const float* base = qkv + (size_t)b * SEQ * (3 * EMB);

    /* q row (pre-scaled by d^-0.5 = 0.125) */
    float q[HD];
    {
        const float* qr = base + (size_t)pos * (3 * EMB) + h * HD;
        #pragma unroll
        for (int d = 0; d < HD; d += 4) {
            float4 t = *(const float4*)(qr + d);
            q[d + 0] = t.x * 0.125f; q[d + 1] = t.y * 0.125f;
            q[d + 2] = t.z * 0.125f; q[d + 3] = t.w * 0.125f;
        }
    }

    float m = -INFINITY, l = 0.f;
    float acc[HD];
    #pragma unroll
    for (int d = 0; d < HD; d++) acc[d] = 0.f;

    const int lrow = tid >> 1;            /* 0..63 smem row this thread fills */
    const int lcol = (tid & 1) * 32;      /* half-row */

    for (int sb = bi - 1; sb <= bi + 1; sb++) {
        if (sb < 0 || sb >= NB) continue;
        for (int half = 0; half < 2; half++) {
            const int krow0 = sb * WIN + half * 64;
            __syncthreads();
            {
                const float* kr = base + (size_t)(krow0 + lrow) * (3 * EMB) + EMB     + h * HD + lcol;
                const float* vr = base + (size_t)(krow0 + lrow) * (3 * EMB) + 2 * EMB + h * HD + lcol;
                #pragma unroll
                for (int i = 0; i < 32; i += 4) {
                    *(float4*)&ks[lrow][lcol + i] = *(const float4*)(kr + i);
                    *(float4*)&vs[lrow][lcol + i] = *(const float4*)(vr + i);
                }
            }
            __syncthreads();

            for (int j = 0; j < 64; j++) {
                float s = 0.f;
                #pragma unroll
                for (int d = 0; d < HD; d += 4) {
                    float4 kv = *(const float4*)&ks[j][d];
                    s += q[d] * kv.x + q[d + 1] * kv.y + q[d + 2] * kv.z + q[d + 3] * kv.w;
                }
                float mn = fmaxf(m, s);
                float corr = __expf(m - mn);   /* 0 on first key (m=-inf) */
                float p = __expf(s - mn);
                l = l * corr + p;
                #pragma unroll
                for (int d = 0; d < HD; d += 4) {
                    float4 vv = *(const float4*)&vs[j][d];
                    acc[d + 0] = acc[d + 0] * corr + p * vv.x;
                    acc[d + 1] = acc[d + 1] * corr + p * vv.y;
                    acc[d + 2] = acc[d + 2] * corr + p * vv.z;
                    acc[d + 3] = acc[d + 3] * corr + p * vv.w;
                }
                m = mn;
            }
        }
    }

    const float inv = 1.f / l;
    float* orow = out + (size_t)(b * SEQ + pos) * EMB + h * HD;
    #pragma unroll
    for (int d = 0; d < HD; d += 4) {
        float4 o;
        o.x = acc[d + 0] * inv; o.y = acc[d + 1] * inv;
        o.z = acc[d + 2] * inv; o.w = acc[d + 3] * inv;
        *(float4*)(orow + d) = o;
    }
}

/* ---------------- launch ---------------- */
extern "C" void kernel_launch(void* const* d_in, const int* in_sizes, int n_in,
                              void* d_out, int out_size)
{
    const float* x     = (const float*)d_in[0];
    const float* ln1w  = (const float*)d_in[1];
    const float* ln1b  = (const float*)d_in[2];
    const float* qkvw  = (const float*)d_in[3];
    const float* qkvb  = (const float*)d_in[4];
    const float* projw = (const float*)d_in[5];
    const float* projb = (const float*)d_in[6];
    const float* ln2w  = (const float*)d_in[7];
    const float* ln2b  = (const float*)d_in[8];
    const float* fc1w  = (const float*)d_in[9];
    const float* fc1b  = (const float*)d_in[10];
    const float* fc2w  = (const float*)d_in[11];
    const float* fc2b  = (const float*)d_in[12];
    float* out = (float*)d_out;

    float *xn, *qkv, *attn, *hbuf;
    cudaGetSymbolAddress((void**)&xn,   g_xnorm);
    cudaGetSymbolAddress((void**)&qkv,  g_qkv);
    cudaGetSymbolAddress((void**)&attn, g_attn);
    cudaGetSymbolAddress((void**)&hbuf, g_hbuf);

    /* 1. LN1 */
    ln_kernel<<<M_TOK, 256>>>(x, ln1w, ln1b, xn);
    /* 2. qkv = xn @ qkv_w^T + qkv_b   (16384 x 3072 x 1024) */
    sgemm_kernel<EPI_NONE><<<dim3(3 * EMB / 128, M_TOK / 128), 256>>>(
        xn, qkvw, qkvb, nullptr, qkv, M_TOK, 3 * EMB, EMB);
    /* 3. local attention */
    lattn_kernel<<<dim3(NB, BATCH * HEADS), 128>>>(qkv, attn);
    /* 4. x1 = x + attn @ proj_w^T + proj_b  -> d_out */
    sgemm_kernel<EPI_ADD><<<dim3(EMB / 128, M_TOK / 128), 256>>>(
        attn, projw, projb, x, out, M_TOK, EMB, EMB);
    /* 5. LN2(x1) -> xn */
    ln_kernel<<<M_TOK, 256>>>(out, ln2w, ln2b, xn);
    /* 6. h = gelu(xn @ fc1_w^T + fc1_b)  (16384 x 4096 x 1024) */
    sgemm_kernel<EPI_GELU><<<dim3(DFF / 128, M_TOK / 128), 256>>>(
        xn, fc1w, fc1b, nullptr, hbuf, M_TOK, DFF, EMB);
    /* 7. out = x1 + h @ fc2_w^T + fc2_b  (16384 x 1024 x 4096) */
    sgemm_kernel<EPI_ADD><<<dim3(EMB / 128, M_TOK / 128), 256>>>(
        hbuf, fc2w, fc2b, out, out, M_TOK, EMB, DFF);
}

// round 3
// speedup vs baseline: 1.5694x; 1.5694x over previous
#include <cuda_runtime.h>
#include <math.h>
#include <stdint.h>

#define BATCH   4
#define SEQ     4096
#define EMB     1024
#define HEADS   16
#define HD      64
#define DFF     4096
#define WIN     128
#define NB      (SEQ / WIN)
#define M_TOK   (BATCH * SEQ)

/* ---------------- scratch ---------------- */
__device__ float g_xnorm[(size_t)M_TOK * EMB];
__device__ float g_qkv[(size_t)M_TOK * 3 * EMB];
__device__ float g_attn[(size_t)M_TOK * EMB];
__device__ float g_hbuf[(size_t)M_TOK * DFF];

/* ---------------- PTX helpers ---------------- */
__device__ __forceinline__ uint32_t f2tf32(float x)
{
    uint32_t r;
    asm("cvt.rna.tf32.f32 %0, %1;" : "=r"(r) : "f"(x));
    return r;
}

__device__ __forceinline__ void mma_tf32(float* d, const uint32_t* a, const uint32_t* b)
{
    asm volatile(
        "mma.sync.aligned.m16n8k8.row.col.f32.tf32.tf32.f32 "
        "{%0,%1,%2,%3},{%4,%5,%6,%7},{%8,%9},{%0,%1,%2,%3};"
        : "+f"(d[0]), "+f"(d[1]), "+f"(d[2]), "+f"(d[3])
        : "r"(a[0]), "r"(a[1]), "r"(a[2]), "r"(a[3]), "r"(b[0]), "r"(b[1]));
}

__device__ __forceinline__ void cp16(void* s, const void* g)
{
    uint32_t sa = (uint32_t)__cvta_generic_to_shared(s);
    asm volatile("cp.async.cg.shared.global [%0], [%1], 16;" :: "r"(sa), "l"(g));
}
__device__ __forceinline__ void cp_commit() { asm volatile("cp.async.commit_group;"); }
__device__ __forceinline__ void cp_wait_all() { asm volatile("cp.async.wait_group 0;"); }

/* ---------------- block reduction ---------------- */
__device__ __forceinline__ float block_sum_1024(float v, float* sh)
{
    #pragma unroll
    for (int o = 16; o > 0; o >>= 1)
        v += __shfl_xor_sync(0xFFFFFFFFu, v, o);
    const int wid = threadIdx.x >> 5;
    const int lane = threadIdx.x & 31;
    if (lane == 0) sh[wid] = v;
    __syncthreads();
    if (wid == 0) {
        float t = (lane < 8) ? sh[lane] : 0.f;
        #pragma unroll
        for (int o = 4; o > 0; o >>= 1)
            t += __shfl_xor_sync(0xFFFFFFFFu, t, o);
        if (lane == 0) sh[8] = t;
    }
    __syncthreads();
    float r = sh[8];
    __syncthreads();
    return r;
}

/* ---------------- LayerNorm ---------------- */
__global__ __launch_bounds__(256)
void ln_kernel(const float* __restrict__ x, const float* __restrict__ w,
               const float* __restrict__ b, float* __restrict__ out)
{
    __shared__ float sh[9];
    const int row = blockIdx.x;
    const int t = threadIdx.x;
    const float* xr = x + (size_t)row * EMB;

    float4 v = *(const float4*)(xr + t * 4);
    float mu = block_sum_1024(v.x + v.y + v.z + v.w, sh) * (1.f / EMB);

    float d0 = v.x - mu, d1 = v.y - mu, d2 = v.z - mu, d3 = v.w - mu;
    float var = block_sum_1024(d0 * d0 + d1 * d1 + d2 * d2 + d3 * d3, sh) * (1.f / EMB);
    float rs = rsqrtf(var + 1e-5f);

    float4 wv = *(const float4*)(w + t * 4);
    float4 bv = *(const float4*)(b + t * 4);
    float4 o;
    o.x = d0 * rs * wv.x + bv.x;
    o.y = d1 * rs * wv.y + bv.y;
    o.z = d2 * rs * wv.z + bv.z;
    o.w = d3 * rs * wv.w + bv.w;
    *(float4*)(out + (size_t)row * EMB + t * 4) = o;
}

/* ---------------- tf32 tensor-core GEMM ----------------
 * C[M,N] = A[M,K] @ B[N,K]^T + bias (+epilogue)
 * 128x128 CTA tile, BK=16, 256 threads / 8 warps, warp tile 64x32.
 * Double-buffered cp.async; padded smem (20 cols) -> conflict-free frags. */
#define EPI_NONE 0
#define EPI_ADD  1
#define EPI_GELU 2

template<int EPI>
__global__ __launch_bounds__(256, 2)
void tgemm_kernel(const float* __restrict__ A, const float* __restrict__ B,
                  const float* __restrict__ bias, const float* __restrict__ R,
                  float* __restrict__ C, int M, int N, int K)
{
    __shared__ float As[2][128][20];
    __shared__ float Bs[2][128][20];

    const int tid = threadIdx.x;
    const int bm = blockIdx.y * 128;
    const int bn = blockIdx.x * 128;

    const int wid = tid >> 5;
    const int lane = tid & 31;
    const int g = lane >> 2;          /* group id 0..7  */
    const int tg = lane & 3;          /* thread-in-group */
    const int warp_m = (wid & 1) * 64;
    const int warp_n = (wid >> 1) * 32;

    /* stage addressing: thread t covers (row = base + t/4, 4-col seg = t%4) */
    const int srow = tid >> 2;        /* 0..63 */
    const int sseg = (tid & 3) * 4;   /* 0,4,8,12 */

    float acc[4][4][4];
    #pragma unroll
    for (int i = 0; i < 4; i++)
        #pragma unroll
        for (int j = 0; j < 4; j++)
            #pragma unroll
            for (int r = 0; r < 4; r++) acc[i][j][r] = 0.f;

    /* prologue: stage k0 = 0 into buf 0 */
    {
        const float* Ab = A + (size_t)bm * K + sseg;
        const float* Bb = B + (size_t)bn * K + sseg;
        #pragma unroll
        for (int h = 0; h < 2; h++) {
            cp16(&As[0][srow + h * 64][sseg], Ab + (size_t)(srow + h * 64) * K);
            cp16(&Bs[0][srow + h * 64][sseg], Bb + (size_t)(srow + h * 64) * K);
        }
        cp_commit();
    }

    int buf = 0;
    for (int k0 = 0; k0 < K; k0 += 16) {
        cp_wait_all();
        __syncthreads();

        if (k0 + 16 < K) {
            const float* Ab = A + (size_t)bm * K + k0 + 16 + sseg;
            const float* Bb = B + (size_t)bn * K + k0 + 16 + sseg;
            #pragma unroll
            for (int h = 0; h < 2; h++) {
                cp16(&As[buf ^ 1][srow + h * 64][sseg], Ab + (size_t)(srow + h * 64) * K);
                cp16(&Bs[buf ^ 1][srow + h * 64][sseg], Bb + (size_t)(srow + h * 64) * K);
            }
            cp_commit();
        }

        #pragma unroll
        for (int ks = 0; ks < 2; ks++) {
            const int kc = ks * 8;
            uint32_t a[4][4], b[4][2];
            #pragma unroll
            for (int mt = 0; mt < 4; mt++) {
                const int r0 = warp_m + mt * 16 + g;
                a[mt][0] = f2tf32(As[buf][r0][kc + tg]);
                a[mt][1] = f2tf32(As[buf][r0 + 8][kc + tg]);
                a[mt][2] = f2tf32(As[buf][r0][kc + tg + 4]);
                a[mt][3] = f2tf32(As[buf][r0 + 8][kc + tg + 4]);
            }
            #pragma unroll
            for (int nt = 0; nt < 4; nt++) {
                const int c0 = warp_n + nt * 8 + g;
                b[nt][0] = f2tf32(Bs[buf][c0][kc + tg]);
                b[nt][1] = f2tf32(Bs[buf][c0][kc + tg + 4]);
            }
            #pragma unroll
            for (int mt = 0; mt < 4; mt++)
                #pragma unroll
                for (int nt = 0; nt < 4; nt++)
                    mma_tf32(acc[mt][nt], a[mt], b[nt]);
        }
        buf ^= 1;
        __syncthreads();
    }

    /* epilogue */
    #pragma unroll
    for (int mt = 0; mt < 4; mt++) {
        #pragma unroll
        for (int h = 0; h < 2; h++) {
            const int row = bm + warp_m + mt * 16 + g + h * 8;
            #pragma unroll
            for (int nt = 0; nt < 4; nt++) {
                const int col = bn + warp_n + nt * 8 + tg * 2;
                float c0 = acc[mt][nt][h * 2 + 0];
                float c1 = acc[mt][nt][h * 2 + 1];
                const float2 bv = *(const float2*)(bias + col);
                c0 += bv.x; c1 += bv.y;
                if (EPI == EPI_ADD) {
                    const float2 rv = *(const float2*)(R + (size_t)row * N + col);
                    c0 += rv.x; c1 += rv.y;
                }
                if (EPI == EPI_GELU) {
                    c0 = 0.5f * c0 * (1.f + erff(c0 * 0.70710678118654752f));
                    c1 = 0.5f * c1 * (1.f + erff(c1 * 0.70710678118654752f));
                }
                float2 o; o.x = c0; o.y = c1;
                *(float2*)(C + (size_t)row * N + col) = o;
            }
        }
    }
}

/* ---------------- local windowed attention ---------------- */
__global__ __launch_bounds__(128)
void lattn_kernel(const float* __restrict__ qkv, float* __restrict__ out)
{
    __shared__ float ks[64][64];
    __shared__ float vs[64][64];

    const int bi = blockIdx.x;
    const int bh = blockIdx.y;
    const int b = bh >> 4, h = bh & 15;
    const int tid = threadIdx.x;
    const int pos = bi * WIN + tid;

    const float* base = qkv + (size_t)b * SEQ * (3 * EMB);

    float q[HD];
    {
        const float* qr = base + (size_t)pos * (3 * EMB) + h * HD;
        #pragma unroll
        for (int d = 0; d < HD; d += 4) {
            float4 t = *(const float4*)(qr + d);
            q[d + 0] = t.x * 0.125f; q[d + 1] = t.y * 0.125f;
            q[d + 2] = t.z * 0.125f; q[d + 3] = t.w * 0.125f;
        }
    }

    float m = -INFINITY, l = 0.f;
    float acc[HD];
    #pragma unroll
    for (int d = 0; d < HD; d++) acc[d] = 0.f;

    const int lrow = tid >> 1;
    const int lcol = (tid & 1) * 32;

    for (int sb = bi - 1; sb <= bi + 1; sb++) {
        if (sb < 0 || sb >= NB) continue;
        for (int half = 0; half < 2; half++) {
            const int krow0 = sb * WIN + half * 64;
            __syncthreads();
            {
                const float* kr = base + (size_t)(krow0 + lrow) * (3 * EMB) + EMB     + h * HD + lcol;
                const float* vr = base + (size_t)(krow0 + lrow) * (3 * EMB) + 2 * EMB + h * HD + lcol;
                #pragma unroll
                for (int i = 0; i < 32; i += 4) {
                    *(float4*)&ks[lrow][lcol + i] = *(const float4*)(kr + i);
                    *(float4*)&vs[lrow][lcol + i] = *(const float4*)(vr + i);
                }
            }
            __syncthreads();

            for (int j = 0; j < 64; j++) {
                float s = 0.f;
                #pragma unroll
                for (int d = 0; d < HD; d += 4) {
                    float4 kv = *(const float4*)&ks[j][d];
                    s += q[d] * kv.x + q[d + 1] * kv.y + q[d + 2] * kv.z + q[d + 3] * kv.w;
                }
                float mn = fmaxf(m, s);
                float corr = __expf(m - mn);
                float p = __expf(s - mn);
                l = l * corr + p;
                #pragma unroll
                for (int d = 0; d < HD; d += 4) {
                    float4 vv = *(const float4*)&vs[j][d];
                    acc[d + 0] = acc[d + 0] * corr + p * vv.x;
                    acc[d + 1] = acc[d + 1] * corr + p * vv.y;
                    acc[d + 2] = acc[d + 2] * corr + p * vv.z;
                    acc[d + 3] = acc[d + 3] * corr + p * vv.w;
                }
                m = mn;
            }
        }
    }

    const float inv = 1.f / l;
    float* orow = out + (size_t)(b * SEQ + pos) * EMB + h * HD;
    #pragma unroll
    for (int d = 0; d < HD; d += 4) {
        float4 o;
        o.x = acc[d + 0] * inv; o.y = acc[d + 1] * inv;
        o.z = acc[d + 2] * inv; o.w = acc[d + 3] * inv;
        *(float4*)(orow + d) = o;
    }
}

/* ---------------- launch ---------------- */
extern "C" void kernel_launch(void* const* d_in, const int* in_sizes, int n_in,
                              void* d_out, int out_size)
{
    const float* x     = (const float*)d_in[0];
    const float* ln1w  = (const float*)d_in[1];
    const float* ln1b  = (const float*)d_in[2];
    const float* qkvw  = (const float*)d_in[3];
    const float* qkvb  = (const float*)d_in[4];
    const float* projw = (const float*)d_in[5];
    const float* projb = (const float*)d_in[6];
    const float* ln2w  = (const float*)d_in[7];
    const float* ln2b  = (const float*)d_in[8];
    const float* fc1w  = (const float*)d_in[9];
    const float* fc1b  = (const float*)d_in[10];
    const float* fc2w  = (const float*)d_in[11];
    const float* fc2b  = (const float*)d_in[12];
    float* out = (float*)d_out;

    float *xn, *qkv, *attn, *hbuf;
    cudaGetSymbolAddress((void**)&xn,   g_xnorm);
    cudaGetSymbolAddress((void**)&qkv,  g_qkv);
    cudaGetSymbolAddress((void**)&attn, g_attn);
    cudaGetSymbolAddress((void**)&hbuf, g_hbuf);

    ln_kernel<<<M_TOK, 256>>>(x, ln1w, ln1b, xn);
    tgemm_kernel<EPI_NONE><<<dim3(3 * EMB / 128, M_TOK / 128), 256>>>(
        xn, qkvw, qkvb, nullptr, qkv, M_TOK, 3 * EMB, EMB);
    lattn_kernel<<<dim3(NB, BATCH * HEADS), 128>>>(qkv, attn);
    tgemm_kernel<EPI_ADD><<<dim3(EMB / 128, M_TOK / 128), 256>>>(
        attn, projw, projb, x, out, M_TOK, EMB, EMB);
    ln_kernel<<<M_TOK, 256>>>(out, ln2w, ln2b, xn);
    tgemm_kernel<EPI_GELU><<<dim3(DFF / 128, M_TOK / 128), 256>>>(
        xn, fc1w, fc1b, nullptr, hbuf, M_TOK, DFF, EMB);
    tgemm_kernel<EPI_ADD><<<dim3(EMB / 128, M_TOK / 128), 256>>>(
        hbuf, fc2w, fc2b, out, out, M_TOK, EMB, DFF);
}

// round 8
// speedup vs baseline: 4.2246x; 2.6919x over previous
#include <cuda_runtime.h>
#include <cuda_fp16.h>
#include <math.h>
#include <stdint.h>

#define BATCH   4
#define SEQ     4096
#define EMB     1024
#define HEADS   16
#define HD      64
#define DFF     4096
#define WIN     128
#define NB      (SEQ / WIN)
#define M_TOK   (BATCH * SEQ)

/* ---------------- scratch ---------------- */
__device__ __half g_xnh[(size_t)M_TOK * EMB];      /* LN out (half)       */
__device__ float  g_qkv[(size_t)M_TOK * 3 * EMB];  /* qkv (fp32)          */
__device__ __half g_attnh[(size_t)M_TOK * EMB];    /* attn out (half)     */
__device__ __half g_hbufh[(size_t)M_TOK * DFF];    /* gelu(fc1) (half)    */
__device__ __half g_wqh[(size_t)3 * EMB * EMB];
__device__ __half g_wph[(size_t)EMB * EMB];
__device__ __half g_w1h[(size_t)DFF * EMB];
__device__ __half g_w2h[(size_t)EMB * DFF];

/* ---------------- PTX helpers ---------------- */
__device__ __forceinline__ void cp16(void* s, const void* g)
{
    uint32_t sa = (uint32_t)__cvta_generic_to_shared(s);
    asm volatile("cp.async.cg.shared.global [%0], [%1], 16;" :: "r"(sa), "l"(g));
}
__device__ __forceinline__ void cp_commit() { asm volatile("cp.async.commit_group;"); }
template<int N>
__device__ __forceinline__ void cp_wait() { asm volatile("cp.async.wait_group %0;" :: "n"(N)); }

__device__ __forceinline__ void mma_f16(float* d, const uint32_t* a, const uint32_t* b)
{
    asm volatile(
        "mma.sync.aligned.m16n8k16.row.col.f32.f16.f16.f32 "
        "{%0,%1,%2,%3},{%4,%5,%6,%7},{%8,%9},{%0,%1,%2,%3};"
        : "+f"(d[0]), "+f"(d[1]), "+f"(d[2]), "+f"(d[3])
        : "r"(a[0]), "r"(a[1]), "r"(a[2]), "r"(a[3]), "r"(b[0]), "r"(b[1]));
}

/* ---------------- fp16 tensor-core GEMM ----------------
 * C[M,N] = A[M,K] @ B[N,K]^T + bias (+epilogue); A,B half, accum fp32.
 * CTA 128x128, BK=32, 256 threads / 8 warps, warp tile 64x32,
 * mma m16n8k16, double-buffered cp.async, pad-40 smem (conflict-free). */
#define EPI_NONE 0
#define EPI_ADD  1
#define EPI_GELU 2

template<int EPI, int OUTH>
__global__ __launch_bounds__(256, 2)
void hgemm(const __half* __restrict__ A, const __half* __restrict__ B,
           const float* __restrict__ bias, const float* __restrict__ R,
           void* __restrict__ Cv, int M, int N, int K)
{
    __shared__ __half As[2][128][40];
    __shared__ __half Bs[2][128][40];

    const int tid = threadIdx.x;
    const int wid = tid >> 5;
    const int lane = tid & 31;
    const int g = lane >> 2;
    const int tg = lane & 3;
    const int bm = blockIdx.y * 128;
    const int bn = blockIdx.x * 128;
    const int warp_m = (wid & 1) * 64;
    const int warp_n = (wid >> 1) * 32;

    /* staging: chunk c -> row=c>>2 (0..127), seg=c&3 (8 halves each) */
    const int srow = tid >> 2;
    const int sseg = tid & 3;

    float acc[4][4][4];
    #pragma unroll
    for (int i = 0; i < 4; i++)
        #pragma unroll
        for (int j = 0; j < 4; j++)
            #pragma unroll
            for (int r = 0; r < 4; r++) acc[i][j][r] = 0.f;

    auto load_stage = [&](int s) {
        const int k0 = s * 32;
        const int buf = s & 1;
        #pragma unroll
        for (int i = 0; i < 2; i++) {
            const int row = srow + i * 64;
            cp16(&As[buf][row][sseg * 8], A + (size_t)(bm + row) * K + k0 + sseg * 8);
            cp16(&Bs[buf][row][sseg * 8], B + (size_t)(bn + row) * K + k0 + sseg * 8);
        }
        cp_commit();
    };

    const int S = K / 32;
    load_stage(0);

    for (int s = 0; s < S; s++) {
        const int buf = s & 1;
        if (s + 1 < S) {
            load_stage(s + 1);
            cp_wait<1>();
        } else {
            cp_wait<0>();
        }
        __syncthreads();

        #pragma unroll
        for (int ks = 0; ks < 2; ks++) {
            const int kc = ks * 16;
            uint32_t a[4][4], b[4][2];
            #pragma unroll
            for (int mt = 0; mt < 4; mt++) {
                const int r0 = warp_m + mt * 16 + g;
                a[mt][0] = *(const uint32_t*)&As[buf][r0][kc + tg * 2];
                a[mt][1] = *(const uint32_t*)&As[buf][r0 + 8][kc + tg * 2];
                a[mt][2] = *(const uint32_t*)&As[buf][r0][kc + tg * 2 + 8];
                a[mt][3] = *(const uint32_t*)&As[buf][r0 + 8][kc + tg * 2 + 8];
            }
            #pragma unroll
            for (int nt = 0; nt < 4; nt++) {
                const int c0 = warp_n + nt * 8 + g;
                b[nt][0] = *(const uint32_t*)&Bs[buf][c0][kc + tg * 2];
                b[nt][1] = *(const uint32_t*)&Bs[buf][c0][kc + tg * 2 + 8];
            }
            #pragma unroll
            for (int mt = 0; mt < 4; mt++)
                #pragma unroll
                for (int nt = 0; nt < 4; nt++)
                    mma_f16(acc[mt][nt], a[mt], b[nt]);
        }
        __syncthreads();
    }

    /* epilogue: c0,c1 = row g cols tg*2,+1 ; c2,c3 = row g+8 */
    #pragma unroll
    for (int mt = 0; mt < 4; mt++) {
        #pragma unroll
        for (int h = 0; h < 2; h++) {
            const int row = bm + warp_m + mt * 16 + g + h * 8;
            #pragma unroll
            for (int nt = 0; nt < 4; nt++) {
                const int col = bn + warp_n + nt * 8 + tg * 2;
                float c0 = acc[mt][nt][h * 2 + 0];
                float c1 = acc[mt][nt][h * 2 + 1];
                const float2 bv = *(const float2*)(bias + col);
                c0 += bv.x; c1 += bv.y;
                if (EPI == EPI_ADD) {
                    const float2 rv = *(const float2*)(R + (size_t)row * N + col);
                    c0 += rv.x; c1 += rv.y;
                }
                if (EPI == EPI_GELU) {
                    c0 = 0.5f * c0 * (1.f + erff(c0 * 0.70710678118654752f));
                    c1 = 0.5f * c1 * (1.f + erff(c1 * 0.70710678118654752f));
                }
                if (OUTH) {
                    __half2* C = (__half2*)Cv;
                    C[((size_t)row * N + col) >> 1] = __floats2half2_rn(c0, c1);
                } else {
                    float2 o; o.x = c0; o.y = c1;
                    *(float2*)((float*)Cv + (size_t)row * N + col) = o;
                }
            }
        }
    }
}

/* ---------------- weight fp32 -> half ---------------- */
__global__ __launch_bounds__(256)
void w2h_kernel(const float* __restrict__ src, __half* __restrict__ dst, int n4)
{
    const int i = blockIdx.x * 256 + threadIdx.x;
    if (i < n4) {
        float4 v = ((const float4*)src)[i];
        __half2* d = (__half2*)(dst + (size_t)i * 4);
        d[0] = __floats2half2_rn(v.x, v.y);
        d[1] = __floats2half2_rn(v.z, v.w);
    }
}

/* ---------------- block reduction ---------------- */
__device__ __forceinline__ float block_sum_1024(float v, float* sh)
{
    #pragma unroll
    for (int o = 16; o > 0; o >>= 1)
        v += __shfl_xor_sync(0xFFFFFFFFu, v, o);
    const int wid = threadIdx.x >> 5;
    const int lane = threadIdx.x & 31;
    if (lane == 0) sh[wid] = v;
    __syncthreads();
    if (wid == 0) {
        float t = (lane < 8) ? sh[lane] : 0.f;
        #pragma unroll
        for (int o = 4; o > 0; o >>= 1)
            t += __shfl_xor_sync(0xFFFFFFFFu, t, o);
        if (lane == 0) sh[8] = t;
    }
    __syncthreads();
    float r = sh[8];
    __syncthreads();
    return r;
}

/* ---------------- LayerNorm -> half ---------------- */
__global__ __launch_bounds__(256)
void ln_kernel(const float* __restrict__ x, const float* __restrict__ w,
               const float* __restrict__ b, __half* __restrict__ out)
{
    __shared__ float sh[9];
    const int row = blockIdx.x;
    const int t = threadIdx.x;
    const float* xr = x + (size_t)row * EMB;

    float4 v = *(const float4*)(xr + t * 4);
    float mu = block_sum_1024(v.x + v.y + v.z + v.w, sh) * (1.f / EMB);

    float d0 = v.x - mu, d1 = v.y - mu, d2 = v.z - mu, d3 = v.w - mu;
    float var = block_sum_1024(d0 * d0 + d1 * d1 + d2 * d2 + d3 * d3, sh) * (1.f / EMB);
    float rs = rsqrtf(var + 1e-5f);

    float4 wv = *(const float4*)(w + t * 4);
    float4 bv = *(const float4*)(b + t * 4);
    __half2* orow = (__half2*)(out + (size_t)row * EMB + t * 4);
    orow[0] = __floats2half2_rn(d0 * rs * wv.x + bv.x, d1 * rs * wv.y + bv.y);
    orow[1] = __floats2half2_rn(d2 * rs * wv.z + bv.z, d3 * rs * wv.w + bv.w);
}

/* ---------------- local windowed attention (chunked two-pass softmax) -------- */
__global__ __launch_bounds__(128)
void lattn_kernel(const float* __restrict__ qkv, __half* __restrict__ out)
{
    __shared__ float ks[64][64];
    __shared__ float vs[64][64];

    const int bi = blockIdx.x;
    const int bh = blockIdx.y;
    const int b = bh >> 4, h = bh & 15;
    const int tid = threadIdx.x;
    const int pos = bi * WIN + tid;

    const float* base = qkv + (size_t)b * SEQ * (3 * EMB);

    float q[HD];
    {
        const float* qr = base + (size_t)pos * (3 * EMB) + h * HD;
        #pragma unroll
        for (int d = 0; d < HD; d += 4) {
            float4 t = *(const float4*)(qr + d);
            q[d + 0] = t.x * 0.125f; q[d + 1] = t.y * 0.125f;
            q[d + 2] = t.z * 0.125f; q[d + 3] = t.w * 0.125f;
        }
    }

    float m = -INFINITY, l = 0.f;
    float acc[HD];
    #pragma unroll
    for (int d = 0; d < HD; d++) acc[d] = 0.f;

    const int lrow = tid >> 1;
    const int lcol = (tid & 1) * 32;

    for (int sb = bi - 1; sb <= bi + 1; sb++) {
        if (sb < 0 || sb >= NB) continue;
        for (int half = 0; half < 2; half++) {
            const int krow0 = sb * WIN + half * 64;
            __syncthreads();
            {
                const float* kr = base + (size_t)(krow0 + lrow) * (3 * EMB) + EMB     + h * HD + lcol;
                const float* vr = base + (size_t)(krow0 + lrow) * (3 * EMB) + 2 * EMB + h * HD + lcol;
                #pragma unroll
                for (int i = 0; i < 32; i += 4) {
                    *(float4*)&ks[lrow][lcol + i] = *(const float4*)(kr + i);
                    *(float4*)&vs[lrow][lcol + i] = *(const float4*)(vr + i);
                }
            }
            __syncthreads();

            #pragma unroll
            for (int c0 = 0; c0 < 64; c0 += 32) {
                float s[32];
                float cmax = -INFINITY;
                #pragma unroll 8
                for (int j = 0; j < 32; j++) {
                    float t = 0.f;
                    #pragma unroll
                    for (int d = 0; d < HD; d += 4) {
                        float4 kv = *(const float4*)&ks[c0 + j][d];
                        t += q[d] * kv.x + q[d + 1] * kv.y + q[d + 2] * kv.z + q[d + 3] * kv.w;
                    }
                    s[j] = t;
                    cmax = fmaxf(cmax, t);
                }
                const float mn = fmaxf(m, cmax);
                const float corr = __expf(m - mn);
                l *= corr;
                #pragma unroll
                for (int d = 0; d < HD; d++) acc[d] *= corr;
                #pragma unroll 8
                for (int j = 0; j < 32; j++) {
                    const float p = __expf(s[j] - mn);
                    l += p;
                    #pragma unroll
                    for (int d = 0; d < HD; d += 4) {
                        float4 vv = *(const float4*)&vs[c0 + j][d];
                        acc[d + 0] += p * vv.x;
                        acc[d + 1] += p * vv.y;
                        acc[d + 2] += p * vv.z;
                        acc[d + 3] += p * vv.w;
                    }
                }
                m = mn;
            }
        }
    }

    const float inv = 1.f / l;
    __half2* orow = (__half2*)(out + (size_t)(b * SEQ + pos) * EMB + h * HD);
    #pragma unroll
    for (int d = 0; d < HD; d += 2)
        orow[d >> 1] = __floats2half2_rn(acc[d] * inv, acc[d + 1] * inv);
}

/* ---------------- launch ---------------- */
extern "C" void kernel_launch(void* const* d_in, const int* in_sizes, int n_in,
                              void* d_out, int out_size)
{
    const float* x     = (const float*)d_in[0];
    const float* ln1w  = (const float*)d_in[1];
    const float* ln1b  = (const float*)d_in[2];
    const float* qkvw  = (const float*)d_in[3];
    const float* qkvb  = (const float*)d_in[4];
    const float* projw = (const float*)d_in[5];
    const float* projb = (const float*)d_in[6];
    const float* ln2w  = (const float*)d_in[7];
    const float* ln2b  = (const float*)d_in[8];
    const float* fc1w  = (const float*)d_in[9];
    const float* fc1b  = (const float*)d_in[10];
    const float* fc2w  = (const float*)d_in[11];
    const float* fc2b  = (const float*)d_in[12];
    float* out = (float*)d_out;

    __half *xnh, *attnh, *hbufh, *wqh, *wph, *w1h, *w2h;
    float *qkv;
    cudaGetSymbolAddress((void**)&xnh,   g_xnh);
    cudaGetSymbolAddress((void**)&qkv,   g_qkv);
    cudaGetSymbolAddress((void**)&attnh, g_attnh);
    cudaGetSymbolAddress((void**)&hbufh, g_hbufh);
    cudaGetSymbolAddress((void**)&wqh,   g_wqh);
    cudaGetSymbolAddress((void**)&wph,   g_wph);
    cudaGetSymbolAddress((void**)&w1h,   g_w1h);
    cudaGetSymbolAddress((void**)&w2h,   g_w2h);

    /* weight fp32 -> half */
    w2h_kernel<<<(3 * EMB * EMB / 4 + 255) / 256, 256>>>(qkvw, wqh, 3 * EMB * EMB / 4);
    w2h_kernel<<<(EMB * EMB / 4 + 255) / 256, 256>>>(projw, wph, EMB * EMB / 4);
    w2h_kernel<<<(DFF * EMB / 4 + 255) / 256, 256>>>(fc1w, w1h, DFF * EMB / 4);
    w2h_kernel<<<(EMB * DFF / 4 + 255) / 256, 256>>>(fc2w, w2h, EMB * DFF / 4);

    /* 1. LN1 -> half */
    ln_kernel<<<M_TOK, 256>>>(x, ln1w, ln1b, xnh);
    /* 2. qkv = xnh @ wq^T + b (fp32 out) */
    hgemm<EPI_NONE, 0><<<dim3(3 * EMB / 128, M_TOK / 128), 256>>>(
        xnh, wqh, qkvb, nullptr, qkv, M_TOK, 3 * EMB, EMB);
    /* 3. local attention -> half */
    lattn_kernel<<<dim3(NB, BATCH * HEADS), 128>>>(qkv, attnh);
    /* 4. x1 = x + attnh @ wp^T + b (fp32 out) */
    hgemm<EPI_ADD, 0><<<dim3(EMB / 128, M_TOK / 128), 256>>>(
        attnh, wph, projb, x, out, M_TOK, EMB, EMB);
    /* 5. LN2 -> half */
    ln_kernel<<<M_TOK, 256>>>(out, ln2w, ln2b, xnh);
    /* 6. hbuf = gelu(xnh @ w1^T + b) -> half */
    hgemm<EPI_GELU, 1><<<dim3(DFF / 128, M_TOK / 128), 256>>>(
        xnh, w1h, fc1b, nullptr, hbufh, M_TOK, DFF, EMB);
    /* 7. out = x1 + hbufh @ w2^T + b (fp32 out) */
    hgemm<EPI_ADD, 0><<<dim3(EMB / 128, M_TOK / 128), 256>>>(
        hbufh, w2h, fc2b, out, out, M_TOK, EMB, DFF);
}